// round 5
// baseline (speedup 1.0000x reference)
#include <cuda_runtime.h>

// Problem constants (fixed by the reference setup)
#define NL 50000      // n_links
#define NP 100000     // n_paths
#define NPAD 100096   // NP rounded up to 128 (scratch row padding)
#define ML 8          // max hops per path
#define D  64         // state dim (link == path)
#define G  192        // 3*D gate width
#define STD 132       // duplicated-A row stride (floats): 128 data + 4 pad

typedef unsigned long long ull;

// ---------------- persistent device scratch (no allocs allowed) -------------
__device__ float g_link_state[NL * D];   // 12.8 MB
__device__ float g_path_state[NP * D];   // 25.6 MB
__device__ float g_GX[NL * G];           // 38.4 MB  (link_state @ Wx_p + b_p)
__device__ float g_M[NL * D];            // 12.8 MB  (segment_sum target)
__device__ float g_R1[NPAD * 256];       // 102.5 MB (selu(PS@W1+b1))
__device__ float g_psdot[NPAD];          // 0.4 MB   (PS . Wf[256:320])

// ---------------- f32x2 packed-FMA helpers (sm_100+) -------------------------
__device__ __forceinline__ ull ffma2(ull a, ull b, ull c) {
    ull d;
    asm("fma.rn.f32x2 %0, %1, %2, %3;" : "=l"(d) : "l"(a), "l"(b), "l"(c));
    return d;
}
__device__ __forceinline__ ull dup2(float x) {
    ull r;
    asm("mov.b64 %0, {%1, %1};" : "=l"(r) : "f"(x));
    return r;
}
__device__ __forceinline__ float2 up2(ull v) {
    float2 f;
    asm("mov.b64 {%0, %1}, %2;" : "=f"(f.x), "=f"(f.y) : "l"(v));
    return f;
}

// ---------------- math helpers ----------------------------------------------
__device__ __forceinline__ float sigm(float x) {
    return __fdividef(1.0f, 1.0f + __expf(-x));
}
__device__ __forceinline__ float ftanh(float x) {
    x = fminf(15.0f, fmaxf(-15.0f, x));
    float e = __expf(2.0f * x);
    return __fdividef(e - 1.0f, e + 1.0f);
}
__device__ __forceinline__ float selu(float x) {
    const float a = 1.6732632423543772f, s = 1.0507009873554805f;
    return x > 0.0f ? s * x : s * a * (__expf(x) - 1.0f);
}

// 4-row x JW-col micro-tile GEMM over K=64.
// A is DUPLICATED smem (value at columns 2k and 2k+1, row stride lda).
// W loaded as longlong2 (LDS.128), pairs land directly in FFMA2 operand regs.
template <int JW>
__device__ __forceinline__ void gemm_dup(const float* __restrict__ sA, int lda, int row0,
                                         const float* __restrict__ sW, int ldw, int col0,
                                         ull (&acc)[4][JW / 2])
{
#pragma unroll 4
    for (int k = 0; k < 64; ++k) {
        ull a2[4];
#pragma unroll
        for (int i = 0; i < 4; ++i)
            a2[i] = *(const ull*)&sA[(row0 + i) * lda + 2 * k];
        const float* wk = &sW[k * ldw + col0];
#pragma unroll
        for (int j4 = 0; j4 < JW / 4; ++j4) {
            longlong2 w = *(const longlong2*)(wk + 4 * j4);
#pragma unroll
            for (int i = 0; i < 4; ++i) {
                acc[i][2 * j4 + 0] = ffma2(a2[i], (ull)w.x, acc[i][2 * j4 + 0]);
                acc[i][2 * j4 + 1] = ffma2(a2[i], (ull)w.y, acc[i][2 * j4 + 1]);
            }
        }
    }
}

// ---------------- kernel: init states ---------------------------------------
__global__ void k_init(const float* __restrict__ cap, const float* __restrict__ traf,
                       int n_links, int n_paths)
{
    int i = blockIdx.x * blockDim.x + threadIdx.x;
    int tot = (n_links + n_paths) * D;
    if (i >= tot) return;
    if (i < n_links * D) {
        int u = i & (D - 1);
        g_link_state[i] = (u == 0) ? cap[i >> 6] : 0.0f;
    } else {
        int j = i - n_links * D;
        int u = j & (D - 1);
        g_path_state[j] = (u == 0) ? traf[j >> 6] : 0.0f;
    }
}

// ---------------- kernel: GX = link_state @ Wx_p + b_p (+ zero g_M) ---------
__global__ void __launch_bounds__(512, 1)
k_gx(const float* __restrict__ W, const float* __restrict__ b, int n_links, int zeroM)
{
    extern __shared__ float sm[];
    float* sW = sm;                 // 64*192 = 12288
    float* sA = sW + 64 * G;        // 128*STD = 16896 (duplicated)
    float* sb = sA + 128 * STD;     // 192
    int tid = threadIdx.x;
    int l0 = blockIdx.x * 128;

    if (zeroM) {
        int base = l0 * D;
        for (int i = tid; i < 128 * D; i += 512) {
            int idx = base + i;
            if (idx < n_links * D) g_M[idx] = 0.0f;
        }
    }
    for (int i = tid; i < 64 * G; i += 512) sW[i] = W[i];
    if (tid < G) sb[tid] = b[tid];
    // duplicated A fill: 128 rows x 16 float4 source chunks
    for (int idx = tid; idx < 128 * 16; idx += 512) {
        int r = idx >> 4, q = idx & 15;
        float4 v = (l0 + r < n_links)
                 ? *(const float4*)&g_link_state[(size_t)(l0 + r) * D + 4 * q]
                 : make_float4(0.f, 0.f, 0.f, 0.f);
        float* dst = &sA[r * STD + 8 * q];
        *(float4*)(dst + 0) = make_float4(v.x, v.x, v.y, v.y);
        *(float4*)(dst + 4) = make_float4(v.z, v.z, v.w, v.w);
    }
    __syncthreads();

    int pg = tid >> 4, cg = tid & 15;
    ull acc[4][6];
#pragma unroll
    for (int i = 0; i < 4; ++i)
#pragma unroll
        for (int j = 0; j < 6; ++j) acc[i][j] = dup2(0.0f);

    gemm_dup<12>(sA, STD, pg * 4, sW, G, cg * 12, acc);

#pragma unroll
    for (int i = 0; i < 4; ++i) {
        int gl = l0 + pg * 4 + i;
        if (gl < n_links) {
            float* dst = &g_GX[(size_t)gl * G + cg * 12];
#pragma unroll
            for (int j2 = 0; j2 < 6; ++j2) {
                float2 v = up2(acc[i][j2]);
                dst[2 * j2 + 0] = v.x + sb[cg * 12 + 2 * j2 + 0];
                dst[2 * j2 + 1] = v.y + sb[cg * 12 + 2 * j2 + 1];
            }
        }
    }
}

// ---------------- kernel: fused path GRU scan --------------------------------
// 64 paths/block, 256 threads, 2 CTAs/SM. Warp-local row exchange (warp w owns
// rows 8w..8w+7). H kept in registers; smem copy is DUPLICATED for LDS.64
// broadcast loads in the GEMM.
__global__ void __launch_bounds__(256, 2)
k_scan(const int* __restrict__ links, const float* __restrict__ Wh,
       int n_paths, int accumM)
{
    extern __shared__ float sm[];
    float* sW = sm;               // 12288
    float* sH = sW + 64 * G;      // 64*STD = 8448 (duplicated)
    int tid = threadIdx.x;
    int p0 = blockIdx.x * 64;
    int pg = tid >> 4, cg = tid & 15;
    int r0 = pg * 4, u0 = cg * 4;

    for (int i = tid; i < 64 * G; i += 256) sW[i] = Wh[i];

    float h[4][4];
    bool valid[4];
#pragma unroll
    for (int i = 0; i < 4; ++i) {
        int p = p0 + r0 + i;
        valid[i] = (p < n_paths);
        float4 v = valid[i] ? *(const float4*)&g_path_state[(size_t)p * D + u0]
                            : make_float4(0.f, 0.f, 0.f, 0.f);
        h[i][0] = v.x; h[i][1] = v.y; h[i][2] = v.z; h[i][3] = v.w;
        float* dst = &sH[(r0 + i) * STD + 2 * u0];
        *(float4*)(dst + 0) = make_float4(v.x, v.x, v.y, v.y);
        *(float4*)(dst + 4) = make_float4(v.z, v.z, v.w, v.w);
    }
    __syncthreads();   // sW loaded + initial sH visible (once, outside loop)

    for (int t = 0; t < ML; ++t) {
        int ln[4];
#pragma unroll
        for (int i = 0; i < 4; ++i) {
            ln[i] = valid[i] ? __ldg(&links[(p0 + r0 + i) * ML + t]) : 0;
            const float* gx = &g_GX[(size_t)ln[i] * G + u0];
            asm volatile("prefetch.global.L1 [%0];" :: "l"(gx));
            asm volatile("prefetch.global.L1 [%0];" :: "l"(gx + 64));
            asm volatile("prefetch.global.L1 [%0];" :: "l"(gx + 128));
        }

        ull az[4][2], ar[4][2], ah[4][2];
#pragma unroll
        for (int i = 0; i < 4; ++i)
#pragma unroll
            for (int j = 0; j < 2; ++j) {
                az[i][j] = dup2(0.0f); ar[i][j] = dup2(0.0f); ah[i][j] = dup2(0.0f);
            }

#pragma unroll 4
        for (int k = 0; k < 64; ++k) {
            ull a2[4];
#pragma unroll
            for (int i = 0; i < 4; ++i)
                a2[i] = *(const ull*)&sH[(r0 + i) * STD + 2 * k];
            const float* wk = &sW[k * G + u0];
            longlong2 wz = *(const longlong2*)(wk);
            longlong2 wr = *(const longlong2*)(wk + 64);
            longlong2 wh = *(const longlong2*)(wk + 128);
#pragma unroll
            for (int i = 0; i < 4; ++i) {
                az[i][0] = ffma2(a2[i], (ull)wz.x, az[i][0]);
                az[i][1] = ffma2(a2[i], (ull)wz.y, az[i][1]);
                ar[i][0] = ffma2(a2[i], (ull)wr.x, ar[i][0]);
                ar[i][1] = ffma2(a2[i], (ull)wr.y, ar[i][1]);
                ah[i][0] = ffma2(a2[i], (ull)wh.x, ah[i][0]);
                ah[i][1] = ffma2(a2[i], (ull)wh.y, ah[i][1]);
            }
        }
        __syncwarp();   // all lanes of my warp done READING sH rows

#pragma unroll
        for (int i = 0; i < 4; ++i) {
            const float* gx = &g_GX[(size_t)ln[i] * G + u0];
            float4 gz = __ldg((const float4*)(gx));
            float4 gr = __ldg((const float4*)(gx + 64));
            float4 gh = __ldg((const float4*)(gx + 128));
            float2 z0 = up2(az[i][0]), z1 = up2(az[i][1]);
            float2 rr0 = up2(ar[i][0]), rr1 = up2(ar[i][1]);
            float2 hh0 = up2(ah[i][0]), hh1 = up2(ah[i][1]);
            float zv[4] = {gz.x + z0.x, gz.y + z0.y, gz.z + z1.x, gz.w + z1.y};
            float rv[4] = {gr.x + rr0.x, gr.y + rr0.y, gr.z + rr1.x, gr.w + rr1.y};
            float hv[4] = {gh.x, gh.y, gh.z, gh.w};
            float gh2[4] = {hh0.x, hh0.y, hh1.x, hh1.y};
#pragma unroll
            for (int j = 0; j < 4; ++j) {
                float z  = sigm(zv[j]);
                float r  = sigm(rv[j]);
                float hc = ftanh(hv[j] + r * gh2[j]);
                h[i][j] = z * h[i][j] + (1.0f - z) * hc;
            }
            float* dst = &sH[(r0 + i) * STD + 2 * u0];
            *(float4*)(dst + 0) = make_float4(h[i][0], h[i][0], h[i][1], h[i][1]);
            *(float4*)(dst + 4) = make_float4(h[i][2], h[i][2], h[i][3], h[i][3]);
            if (accumM && valid[i]) {
                float* m = &g_M[(size_t)ln[i] * D + u0];
#pragma unroll
                for (int j = 0; j < 4; ++j) atomicAdd(m + j, h[i][j]);
            }
        }
        __syncwarp();   // sH writes visible to my warp before next GEMM
    }

#pragma unroll
    for (int i = 0; i < 4; ++i)
        if (valid[i])
            *(float4*)&g_path_state[(size_t)(p0 + r0 + i) * D + u0] =
                make_float4(h[i][0], h[i][1], h[i][2], h[i][3]);
}

// ---------------- kernel: link GRU (fused dual GEMM, gates in registers) -----
__global__ void __launch_bounds__(512, 1)
k_lgru(const float* __restrict__ Wx, const float* __restrict__ Wh,
       const float* __restrict__ b, int n_links)
{
    extern __shared__ float sm[];
    float* sWx = sm;                // 12288
    float* sWh = sWx + 12288;       // 12288
    float* sM  = sWh + 12288;       // 64*STD = 8448 (duplicated)
    float* sLS = sM + 64 * STD;     // 8448 (duplicated)
    int tid = threadIdx.x;
    int l0 = blockIdx.x * 64;
    int pg = tid >> 4, cg = tid & 15;   // 32 row-groups x 16 col-groups
    int r0 = pg * 2, u0 = cg * 4;

    for (int i = tid; i < 12288; i += 512) { sWx[i] = Wx[i]; sWh[i] = Wh[i]; }
    for (int idx = tid; idx < 64 * 16; idx += 512) {
        int r = idx >> 4, q = idx & 15;
        bool v = (l0 + r < n_links);
        float4 m4 = v ? *(const float4*)&g_M[(size_t)(l0 + r) * D + 4 * q]
                      : make_float4(0.f, 0.f, 0.f, 0.f);
        float4 l4 = v ? *(const float4*)&g_link_state[(size_t)(l0 + r) * D + 4 * q]
                      : make_float4(0.f, 0.f, 0.f, 0.f);
        float* dm = &sM[r * STD + 8 * q];
        *(float4*)(dm + 0) = make_float4(m4.x, m4.x, m4.y, m4.y);
        *(float4*)(dm + 4) = make_float4(m4.z, m4.z, m4.w, m4.w);
        float* dl = &sLS[r * STD + 8 * q];
        *(float4*)(dl + 0) = make_float4(l4.x, l4.x, l4.y, l4.y);
        *(float4*)(dl + 4) = make_float4(l4.z, l4.z, l4.w, l4.w);
    }
    __syncthreads();

    ull xz[2][2], xr[2][2], xh[2][2];
    ull hz[2][2], hr[2][2], hh[2][2];
#pragma unroll
    for (int i = 0; i < 2; ++i)
#pragma unroll
        for (int j = 0; j < 2; ++j) {
            xz[i][j] = dup2(0.f); xr[i][j] = dup2(0.f); xh[i][j] = dup2(0.f);
            hz[i][j] = dup2(0.f); hr[i][j] = dup2(0.f); hh[i][j] = dup2(0.f);
        }

#pragma unroll 4
    for (int k = 0; k < 64; ++k) {
        ull am[2], al[2];
#pragma unroll
        for (int i = 0; i < 2; ++i) {
            am[i] = *(const ull*)&sM[(r0 + i) * STD + 2 * k];
            al[i] = *(const ull*)&sLS[(r0 + i) * STD + 2 * k];
        }
        const float* wx = &sWx[k * G + u0];
        const float* wh = &sWh[k * G + u0];
        longlong2 xzv = *(const longlong2*)(wx);
        longlong2 xrv = *(const longlong2*)(wx + 64);
        longlong2 xhv = *(const longlong2*)(wx + 128);
        longlong2 hzv = *(const longlong2*)(wh);
        longlong2 hrv = *(const longlong2*)(wh + 64);
        longlong2 hhv = *(const longlong2*)(wh + 128);
#pragma unroll
        for (int i = 0; i < 2; ++i) {
            xz[i][0] = ffma2(am[i], (ull)xzv.x, xz[i][0]);
            xz[i][1] = ffma2(am[i], (ull)xzv.y, xz[i][1]);
            xr[i][0] = ffma2(am[i], (ull)xrv.x, xr[i][0]);
            xr[i][1] = ffma2(am[i], (ull)xrv.y, xr[i][1]);
            xh[i][0] = ffma2(am[i], (ull)xhv.x, xh[i][0]);
            xh[i][1] = ffma2(am[i], (ull)xhv.y, xh[i][1]);
            hz[i][0] = ffma2(al[i], (ull)hzv.x, hz[i][0]);
            hz[i][1] = ffma2(al[i], (ull)hzv.y, hz[i][1]);
            hr[i][0] = ffma2(al[i], (ull)hrv.x, hr[i][0]);
            hr[i][1] = ffma2(al[i], (ull)hrv.y, hr[i][1]);
            hh[i][0] = ffma2(al[i], (ull)hhv.x, hh[i][0]);
            hh[i][1] = ffma2(al[i], (ull)hhv.y, hh[i][1]);
        }
    }

#pragma unroll
    for (int i = 0; i < 2; ++i) {
        int gl = l0 + r0 + i;
        if (gl < n_links) {
            float2 a0 = up2(xz[i][0]), a1 = up2(xz[i][1]);
            float2 b0 = up2(xr[i][0]), b1 = up2(xr[i][1]);
            float2 c0 = up2(xh[i][0]), c1 = up2(xh[i][1]);
            float2 d0 = up2(hz[i][0]), d1 = up2(hz[i][1]);
            float2 e0 = up2(hr[i][0]), e1 = up2(hr[i][1]);
            float2 f0 = up2(hh[i][0]), f1 = up2(hh[i][1]);
            float zin[4] = {a0.x + d0.x, a0.y + d0.y, a1.x + d1.x, a1.y + d1.y};
            float rin[4] = {b0.x + e0.x, b0.y + e0.y, b1.x + e1.x, b1.y + e1.y};
            float xhg[4] = {c0.x, c0.y, c1.x, c1.y};
            float hhg[4] = {f0.x, f0.y, f1.x, f1.y};
            float4 outv;
            float* ov = (float*)&outv;
#pragma unroll
            for (int j = 0; j < 4; ++j) {
                int u = u0 + j;
                float z  = sigm(zin[j] + b[u]);
                float r  = sigm(rin[j] + b[64 + u]);
                float hc = ftanh(xhg[j] + b[128 + u] + r * hhg[j]);
                float hs = sLS[(r0 + i) * STD + 2 * u];
                ov[j] = z * hs + (1.0f - z) * hc;
            }
            *(float4*)&g_link_state[(size_t)gl * D + u0] = outv;
        }
    }
}

// ---------------- kernel: readout stage 1 ------------------------------------
// g_R1 = selu(PS @ W1 + b1); g_psdot = PS . Wf[256:320]
__global__ void __launch_bounds__(256, 2)
k_r1(const float* __restrict__ W1, const float* __restrict__ b1,
     const float* __restrict__ Wf, int n_paths)
{
    extern __shared__ float sm[];
    float* sPS = sm;                  // 64*STD = 8448 (duplicated)
    float* sW  = sPS + 64 * STD;      // 64*260 = 16640
    float* sw2 = sW + 16640;          // 64 (Wf[256:320])
    int tid = threadIdx.x;
    int p0 = blockIdx.x * 64;

    for (int idx = tid; idx < 64 * 16; idx += 256) {
        int r = idx >> 4, q = idx & 15;
        float4 v = (p0 + r < n_paths)
                 ? *(const float4*)&g_path_state[(size_t)(p0 + r) * D + 4 * q]
                 : make_float4(0.f, 0.f, 0.f, 0.f);
        float* dst = &sPS[r * STD + 8 * q];
        *(float4*)(dst + 0) = make_float4(v.x, v.x, v.y, v.y);
        *(float4*)(dst + 4) = make_float4(v.z, v.z, v.w, v.w);
    }
    for (int idx = tid; idx < 64 * 64; idx += 256) {
        int k = idx >> 6, q = idx & 63;
        *(float4*)&sW[k * 260 + q * 4] = *(const float4*)&W1[k * 256 + q * 4];
    }
    if (tid < 64) sw2[tid] = Wf[256 + tid];
    __syncthreads();

    int pg = tid >> 4, cg = tid & 15;
    int r0 = pg * 4, c0 = cg * 16;

    ull acc[4][8];
#pragma unroll
    for (int i = 0; i < 4; ++i)
#pragma unroll
        for (int j = 0; j < 8; ++j) acc[i][j] = dup2(0.0f);
    gemm_dup<16>(sPS, STD, r0, sW, 260, c0, acc);

#pragma unroll
    for (int i = 0; i < 4; ++i) {
        float* dst = &g_R1[(size_t)(p0 + r0 + i) * 256 + c0];
#pragma unroll
        for (int q = 0; q < 4; ++q) {
            float2 va = up2(acc[i][2 * q]);
            float2 vb = up2(acc[i][2 * q + 1]);
            float4 o;
            o.x = selu(va.x + __ldg(&b1[c0 + 4 * q + 0]));
            o.y = selu(va.y + __ldg(&b1[c0 + 4 * q + 1]));
            o.z = selu(vb.x + __ldg(&b1[c0 + 4 * q + 2]));
            o.w = selu(vb.y + __ldg(&b1[c0 + 4 * q + 3]));
            *(float4*)(dst + 4 * q) = o;
        }
    }

    if (tid < 64) {
        float d = 0.0f;
#pragma unroll 8
        for (int u = 0; u < 64; ++u) d += sPS[tid * STD + 2 * u] * sw2[u];
        g_psdot[p0 + tid] = d;
    }
}

// ---------------- kernel: readout stage 2 ------------------------------------
// out = selu(R1 @ W2 + b2) . Wf[0:256] + psdot + bf
__global__ void __launch_bounds__(256, 2)
k_r2(const float* __restrict__ W2, const float* __restrict__ b2,
     const float* __restrict__ Wf, const float* __restrict__ bf,
     float* __restrict__ out, int n_paths)
{
    extern __shared__ float sm[];
    float* sA = sm;                  // 64*STD = 8448 (duplicated R1 K-chunk)
    float* sW = sA + 64 * STD;       // 64*260 = 16640 (W2 K-chunk)
    int tid = threadIdx.x;
    int p0 = blockIdx.x * 64;
    int pg = tid >> 4, cg = tid & 15;
    int r0 = pg * 4, c0 = cg * 16;

    ull acc[4][8];
#pragma unroll
    for (int i = 0; i < 4; ++i)
#pragma unroll
        for (int j = 0; j < 8; ++j) acc[i][j] = dup2(0.0f);

    for (int kc = 0; kc < 4; ++kc) {
        for (int idx = tid; idx < 64 * 16; idx += 256) {
            int r = idx >> 4, q = idx & 15;
            float4 v = *(const float4*)&g_R1[(size_t)(p0 + r) * 256 + kc * 64 + 4 * q];
            float* dst = &sA[r * STD + 8 * q];
            *(float4*)(dst + 0) = make_float4(v.x, v.x, v.y, v.y);
            *(float4*)(dst + 4) = make_float4(v.z, v.z, v.w, v.w);
        }
        for (int idx = tid; idx < 64 * 64; idx += 256) {
            int k = idx >> 6, q = idx & 63;
            *(float4*)&sW[k * 260 + q * 4] =
                *(const float4*)&W2[(size_t)(kc * 64 + k) * 256 + q * 4];
        }
        __syncthreads();
        gemm_dup<16>(sA, STD, r0, sW, 260, c0, acc);
        __syncthreads();
    }

    float part[4];
#pragma unroll
    for (int i = 0; i < 4; ++i) {
        float s = 0.0f;
#pragma unroll
        for (int j2 = 0; j2 < 8; ++j2) {
            float2 v = up2(acc[i][j2]);
            int c = c0 + 2 * j2;
            s += selu(v.x + __ldg(&b2[c + 0])) * __ldg(&Wf[c + 0]);
            s += selu(v.y + __ldg(&b2[c + 1])) * __ldg(&Wf[c + 1]);
        }
        part[i] = s;
    }
#pragma unroll
    for (int i = 0; i < 4; ++i) {
#pragma unroll
        for (int off = 8; off > 0; off >>= 1)
            part[i] += __shfl_xor_sync(0xffffffffu, part[i], off, 16);
    }
    if (cg == 0) {
#pragma unroll
        for (int i = 0; i < 4; ++i) {
            int p = p0 + r0 + i;
            if (p < n_paths)
                out[p] = part[i] + g_psdot[p] + __ldg(&bf[0]);
        }
    }
}

// ---------------- host launcher ----------------------------------------------
extern "C" void kernel_launch(void* const* d_in, const int* in_sizes, int n_in,
                              void* d_out, int out_size)
{
    const float* cap  = (const float*)d_in[0];
    const float* traf = (const float*)d_in[1];
    const int*   links= (const int*)d_in[2];
    // d_in[3] = paths, d_in[4] = seqs : structurally e = p*ML + t, unused
    const float* Wx_p = (const float*)d_in[5];
    const float* Wh_p = (const float*)d_in[6];
    const float* b_p  = (const float*)d_in[7];
    const float* Wx_e = (const float*)d_in[8];
    const float* Wh_e = (const float*)d_in[9];
    const float* b_e  = (const float*)d_in[10];
    const float* W1   = (const float*)d_in[11];
    const float* b1   = (const float*)d_in[12];
    const float* W2   = (const float*)d_in[13];
    const float* b2   = (const float*)d_in[14];
    const float* Wf   = (const float*)d_in[15];
    const float* bf   = (const float*)d_in[16];

    int n_links = in_sizes[0];
    int n_paths = in_sizes[1];
    float* out = (float*)d_out;

    const int SM_GX   = (12288 + 128 * STD + 192) * 4;
    const int SM_SCAN = (12288 + 64 * STD) * 4;
    const int SM_LGRU = (12288 + 12288 + 64 * STD + 64 * STD) * 4;
    const int SM_R1   = (64 * STD + 16640 + 64) * 4;
    const int SM_R2   = (64 * STD + 16640) * 4;

    static bool attrs_set = false;
    if (!attrs_set) {
        cudaFuncSetAttribute(k_gx,   cudaFuncAttributeMaxDynamicSharedMemorySize, SM_GX);
        cudaFuncSetAttribute(k_scan, cudaFuncAttributeMaxDynamicSharedMemorySize, SM_SCAN);
        cudaFuncSetAttribute(k_lgru, cudaFuncAttributeMaxDynamicSharedMemorySize, SM_LGRU);
        cudaFuncSetAttribute(k_r1,   cudaFuncAttributeMaxDynamicSharedMemorySize, SM_R1);
        cudaFuncSetAttribute(k_r2,   cudaFuncAttributeMaxDynamicSharedMemorySize, SM_R2);
        attrs_set = true;
    }

    k_init<<<((n_links + n_paths) * D + 255) / 256, 256>>>(cap, traf, n_links, n_paths);

    for (int it = 0; it < 3; ++it) {
        bool last = (it == 2);
        k_gx<<<(n_links + 127) / 128, 512, SM_GX>>>(Wx_p, b_p, n_links, last ? 0 : 1);
        k_scan<<<(n_paths + 63) / 64, 256, SM_SCAN>>>(links, Wh_p, n_paths, last ? 0 : 1);
        if (!last)
            k_lgru<<<(n_links + 63) / 64, 512, SM_LGRU>>>(Wx_e, Wh_e, b_e, n_links);
    }

    int gread = (n_paths + 63) / 64;
    k_r1<<<gread, 256, SM_R1>>>(W1, b1, Wf, n_paths);
    k_r2<<<gread, 256, SM_R2>>>(W2, b2, Wf, bf, out, n_paths);
}

// round 6
// speedup vs baseline: 1.0958x; 1.0958x over previous
#include <cuda_runtime.h>

// Problem constants (fixed by the reference setup)
#define NL 50000      // n_links
#define NP 100000     // n_paths
#define NPAD 100096   // NP rounded up to 128 (scratch row padding)
#define ML 8          // max hops per path
#define D  64         // state dim (link == path)
#define G  192        // 3*D gate width
#define SH 68         // sH row stride (floats)

typedef unsigned long long ull;

// ---------------- persistent device scratch (no allocs allowed) -------------
__device__ float g_link_state[NL * D];   // 12.8 MB
__device__ float g_path_state[NP * D];   // 25.6 MB
__device__ float g_GX[NL * G];           // 38.4 MB  (link_state @ Wx_p + b_p)
__device__ float g_M[NL * D];            // 12.8 MB  (segment_sum target)
__device__ float g_R1[NPAD * 256];       // 102.5 MB (selu(PS@W1+b1))
__device__ float g_psdot[NPAD];          // 0.4 MB   (PS . Wf[256:320])

// ---------------- f32x2 packed-FMA helpers (sm_100+) -------------------------
__device__ __forceinline__ ull ffma2(ull a, ull b, ull c) {
    ull d;
    asm("fma.rn.f32x2 %0, %1, %2, %3;" : "=l"(d) : "l"(a), "l"(b), "l"(c));
    return d;
}
__device__ __forceinline__ ull dup2(float x) {
    ull r;
    asm("mov.b64 %0, {%1, %1};" : "=l"(r) : "f"(x));
    return r;
}
__device__ __forceinline__ float2 up2(ull v) {
    float2 f;
    asm("mov.b64 {%0, %1}, %2;" : "=f"(f.x), "=f"(f.y) : "l"(v));
    return f;
}

// ---------------- math helpers ----------------------------------------------
__device__ __forceinline__ float sigm(float x) {
    return __fdividef(1.0f, 1.0f + __expf(-x));
}
__device__ __forceinline__ float ftanh(float x) {
    x = fminf(15.0f, fmaxf(-15.0f, x));
    float e = __expf(2.0f * x);
    return __fdividef(e - 1.0f, e + 1.0f);
}
__device__ __forceinline__ float selu(float x) {
    const float a = 1.6732632423543772f, s = 1.0507009873554805f;
    return x > 0.0f ? s * x : s * a * (__expf(x) - 1.0f);
}

// 4-row x JW-col register micro-tile GEMM over K=64, packed f32x2 FMAs.
// Accumulates into acc (caller initializes).
template <int JW>
__device__ __forceinline__ void gemm_rows4_x2(const float* __restrict__ sA, int lda, int row0,
                                              const float* __restrict__ sW, int ldw, int col0,
                                              ull (&acc)[4][JW / 2])
{
#pragma unroll 4
    for (int k = 0; k < 64; ++k) {
        ull a2[4];
#pragma unroll
        for (int i = 0; i < 4; ++i) a2[i] = dup2(sA[(row0 + i) * lda + k]);
        const float* wk = &sW[k * ldw + col0];
#pragma unroll
        for (int j2 = 0; j2 < JW / 2; ++j2) {
            ull w = *(const ull*)(wk + 2 * j2);
#pragma unroll
            for (int i = 0; i < 4; ++i) acc[i][j2] = ffma2(a2[i], w, acc[i][j2]);
        }
    }
}

// ---------------- kernel: init states ---------------------------------------
__global__ void k_init(const float* __restrict__ cap, const float* __restrict__ traf,
                       int n_links, int n_paths)
{
    int i = blockIdx.x * blockDim.x + threadIdx.x;
    int tot = (n_links + n_paths) * D;
    if (i >= tot) return;
    if (i < n_links * D) {
        int u = i & (D - 1);
        g_link_state[i] = (u == 0) ? cap[i >> 6] : 0.0f;
    } else {
        int j = i - n_links * D;
        int u = j & (D - 1);
        g_path_state[j] = (u == 0) ? traf[j >> 6] : 0.0f;
    }
}

// ---------------- kernel: GX = link_state @ Wx_p + b_p (+ zero g_M) ---------
// 64 links/block, 256 threads, 2 CTAs/SM.
__global__ void __launch_bounds__(256, 2)
k_gx(const float* __restrict__ W, const float* __restrict__ b, int n_links, int zeroM)
{
    extern __shared__ float sm[];
    float* sW = sm;                 // 64*192 = 12288
    float* sA = sW + 64 * G;        // 64*65 = 4160
    float* sb = sA + 64 * 65;       // 192
    int tid = threadIdx.x;
    int l0 = blockIdx.x * 64;

    if (zeroM) {
        int base = l0 * D;
        for (int i = tid; i < 64 * D; i += 256) {
            int idx = base + i;
            if (idx < n_links * D) g_M[idx] = 0.0f;
        }
    }
    for (int i = tid; i < 64 * G; i += 256) sW[i] = W[i];
    if (tid < G) sb[tid] = b[tid];
    for (int idx = tid; idx < 64 * D; idx += 256) {
        int r = idx >> 6, u = idx & 63;
        sA[r * 65 + u] = (l0 + r < n_links) ? g_link_state[(size_t)(l0 + r) * D + u] : 0.0f;
    }
    __syncthreads();

    int pg = tid >> 4, cg = tid & 15;   // 16 row-groups x 16 col-groups
    ull acc[4][6];
#pragma unroll
    for (int i = 0; i < 4; ++i)
#pragma unroll
        for (int j = 0; j < 6; ++j) acc[i][j] = dup2(0.0f);

    gemm_rows4_x2<12>(sA, 65, pg * 4, sW, G, cg * 12, acc);

#pragma unroll
    for (int i = 0; i < 4; ++i) {
        int gl = l0 + pg * 4 + i;
        if (gl < n_links) {
            float* dst = &g_GX[(size_t)gl * G + cg * 12];
#pragma unroll
            for (int j2 = 0; j2 < 6; ++j2) {
                float2 v = up2(acc[i][j2]);
                dst[2 * j2 + 0] = v.x + sb[cg * 12 + 2 * j2 + 0];
                dst[2 * j2 + 1] = v.y + sb[cg * 12 + 2 * j2 + 1];
            }
        }
    }
}

// ---------------- kernel: fused path GRU scan --------------------------------
// 64 paths/block, 256 threads, 2 CTAs/SM. Row exchange is half-warp-local
// (threads with the same pg are 16 consecutive lanes); H kept in registers,
// double-buffered smem copy as GEMM A operand -> ONE __syncwarp per step.
__global__ void __launch_bounds__(256, 2)
k_scan(const int* __restrict__ links, const float* __restrict__ Wh,
       int n_paths, int accumM)
{
    extern __shared__ float sm[];
    float* sW  = sm;               // 12288
    float* sHb = sW + 64 * G;      // 2 * 64*SH = 8704 (double buffer)
    int tid = threadIdx.x;
    int p0 = blockIdx.x * 64;
    int pg = tid >> 4, cg = tid & 15;
    int r0 = pg * 4, u0 = cg * 4;

    for (int i = tid; i < 64 * G; i += 256) sW[i] = Wh[i];

    float h[4][4];
    bool valid[4];
#pragma unroll
    for (int i = 0; i < 4; ++i) {
        int p = p0 + r0 + i;
        valid[i] = (p < n_paths);
        float4 v = valid[i] ? *(const float4*)&g_path_state[(size_t)p * D + u0]
                            : make_float4(0.f, 0.f, 0.f, 0.f);
        h[i][0] = v.x; h[i][1] = v.y; h[i][2] = v.z; h[i][3] = v.w;
        *(float4*)&sHb[(r0 + i) * SH + u0] = v;
    }
    __syncthreads();   // sW loaded + initial sH (buffer 0) visible

    int cur = 0;
    for (int t = 0; t < ML; ++t) {
        const float* Hc = sHb + cur * (64 * SH);
        float* Hn = sHb + (cur ^ 1) * (64 * SH);

        int ln[4];
#pragma unroll
        for (int i = 0; i < 4; ++i) {
            ln[i] = valid[i] ? __ldg(&links[(p0 + r0 + i) * ML + t]) : 0;
            const float* gx = &g_GX[(size_t)ln[i] * G + u0];
            asm volatile("prefetch.global.L1 [%0];" :: "l"(gx));
            asm volatile("prefetch.global.L1 [%0];" :: "l"(gx + 64));
            asm volatile("prefetch.global.L1 [%0];" :: "l"(gx + 128));
        }

        ull az[4][2], ar[4][2], ah[4][2];
#pragma unroll
        for (int i = 0; i < 4; ++i)
#pragma unroll
            for (int j = 0; j < 2; ++j) {
                az[i][j] = dup2(0.0f); ar[i][j] = dup2(0.0f); ah[i][j] = dup2(0.0f);
            }

#pragma unroll 4
        for (int k = 0; k < 64; ++k) {
            ull a2[4];
#pragma unroll
            for (int i = 0; i < 4; ++i) a2[i] = dup2(Hc[(r0 + i) * SH + k]);
            const float* wk = &sW[k * G + u0];
            ull wz0 = *(const ull*)(wk + 0),   wz1 = *(const ull*)(wk + 2);
            ull wr0 = *(const ull*)(wk + 64),  wr1 = *(const ull*)(wk + 66);
            ull wh0 = *(const ull*)(wk + 128), wh1 = *(const ull*)(wk + 130);
#pragma unroll
            for (int i = 0; i < 4; ++i) {
                az[i][0] = ffma2(a2[i], wz0, az[i][0]);
                az[i][1] = ffma2(a2[i], wz1, az[i][1]);
                ar[i][0] = ffma2(a2[i], wr0, ar[i][0]);
                ar[i][1] = ffma2(a2[i], wr1, ar[i][1]);
                ah[i][0] = ffma2(a2[i], wh0, ah[i][0]);
                ah[i][1] = ffma2(a2[i], wh1, ah[i][1]);
            }
        }

#pragma unroll
        for (int i = 0; i < 4; ++i) {
            const float* gx = &g_GX[(size_t)ln[i] * G + u0];
            float4 gz = __ldg((const float4*)(gx));
            float4 gr = __ldg((const float4*)(gx + 64));
            float4 gh = __ldg((const float4*)(gx + 128));
            float2 z0 = up2(az[i][0]), z1 = up2(az[i][1]);
            float2 rr0 = up2(ar[i][0]), rr1 = up2(ar[i][1]);
            float2 hh0 = up2(ah[i][0]), hh1 = up2(ah[i][1]);
            float zv[4] = {gz.x + z0.x, gz.y + z0.y, gz.z + z1.x, gz.w + z1.y};
            float rv[4] = {gr.x + rr0.x, gr.y + rr0.y, gr.z + rr1.x, gr.w + rr1.y};
            float hv[4] = {gh.x, gh.y, gh.z, gh.w};
            float gh2[4] = {hh0.x, hh0.y, hh1.x, hh1.y};
#pragma unroll
            for (int j = 0; j < 4; ++j) {
                float z  = sigm(zv[j]);
                float r  = sigm(rv[j]);
                float hc = ftanh(hv[j] + r * gh2[j]);
                h[i][j] = z * h[i][j] + (1.0f - z) * hc;
            }
            *(float4*)&Hn[(r0 + i) * SH + u0] =
                make_float4(h[i][0], h[i][1], h[i][2], h[i][3]);
            if (accumM && valid[i]) {
                float* m = &g_M[(size_t)ln[i] * D + u0];
#pragma unroll
                for (int j = 0; j < 4; ++j) atomicAdd(m + j, h[i][j]);
            }
        }
        cur ^= 1;
        __syncwarp();   // half-warp's writes to the new buffer visible
    }

#pragma unroll
    for (int i = 0; i < 4; ++i)
        if (valid[i])
            *(float4*)&g_path_state[(size_t)(p0 + r0 + i) * D + u0] =
                make_float4(h[i][0], h[i][1], h[i][2], h[i][3]);
}

// ---------------- kernel: link GRU (fused dual GEMM, gates in registers) -----
__global__ void __launch_bounds__(512, 1)
k_lgru(const float* __restrict__ Wx, const float* __restrict__ Wh,
       const float* __restrict__ b, int n_links)
{
    extern __shared__ float sm[];
    float* sWx = sm;                // 12288
    float* sWh = sWx + 12288;       // 12288
    float* sM  = sWh + 12288;       // 64*65 = 4160
    float* sLS = sM + 4160;         // 4160
    int tid = threadIdx.x;
    int l0 = blockIdx.x * 64;
    int pg = tid >> 4, cg = tid & 15;   // 32 row-groups x 16 col-groups
    int r0 = pg * 2, u0 = cg * 4;

    for (int i = tid; i < 12288; i += 512) { sWx[i] = Wx[i]; sWh[i] = Wh[i]; }
    for (int idx = tid; idx < 64 * D; idx += 512) {
        int r = idx >> 6, u = idx & 63;
        bool v = (l0 + r < n_links);
        sM[r * 65 + u]  = v ? g_M[(size_t)(l0 + r) * D + u] : 0.0f;
        sLS[r * 65 + u] = v ? g_link_state[(size_t)(l0 + r) * D + u] : 0.0f;
    }
    __syncthreads();

    ull xz[2][2], xr[2][2], xh[2][2];
    ull hz[2][2], hr[2][2], hh[2][2];
#pragma unroll
    for (int i = 0; i < 2; ++i)
#pragma unroll
        for (int j = 0; j < 2; ++j) {
            xz[i][j] = dup2(0.f); xr[i][j] = dup2(0.f); xh[i][j] = dup2(0.f);
            hz[i][j] = dup2(0.f); hr[i][j] = dup2(0.f); hh[i][j] = dup2(0.f);
        }

#pragma unroll 4
    for (int k = 0; k < 64; ++k) {
        ull am[2], al[2];
#pragma unroll
        for (int i = 0; i < 2; ++i) {
            am[i] = dup2(sM[(r0 + i) * 65 + k]);
            al[i] = dup2(sLS[(r0 + i) * 65 + k]);
        }
        const float* wx = &sWx[k * G + u0];
        const float* wh = &sWh[k * G + u0];
        ull xz0 = *(const ull*)(wx + 0),   xz1 = *(const ull*)(wx + 2);
        ull xr0 = *(const ull*)(wx + 64),  xr1 = *(const ull*)(wx + 66);
        ull xh0 = *(const ull*)(wx + 128), xh1 = *(const ull*)(wx + 130);
        ull hz0 = *(const ull*)(wh + 0),   hz1 = *(const ull*)(wh + 2);
        ull hr0 = *(const ull*)(wh + 64),  hr1 = *(const ull*)(wh + 66);
        ull hh0 = *(const ull*)(wh + 128), hh1 = *(const ull*)(wh + 130);
#pragma unroll
        for (int i = 0; i < 2; ++i) {
            xz[i][0] = ffma2(am[i], xz0, xz[i][0]);
            xz[i][1] = ffma2(am[i], xz1, xz[i][1]);
            xr[i][0] = ffma2(am[i], xr0, xr[i][0]);
            xr[i][1] = ffma2(am[i], xr1, xr[i][1]);
            xh[i][0] = ffma2(am[i], xh0, xh[i][0]);
            xh[i][1] = ffma2(am[i], xh1, xh[i][1]);
            hz[i][0] = ffma2(al[i], hz0, hz[i][0]);
            hz[i][1] = ffma2(al[i], hz1, hz[i][1]);
            hr[i][0] = ffma2(al[i], hr0, hr[i][0]);
            hr[i][1] = ffma2(al[i], hr1, hr[i][1]);
            hh[i][0] = ffma2(al[i], hh0, hh[i][0]);
            hh[i][1] = ffma2(al[i], hh1, hh[i][1]);
        }
    }

#pragma unroll
    for (int i = 0; i < 2; ++i) {
        int gl = l0 + r0 + i;
        if (gl < n_links) {
            float2 a0 = up2(xz[i][0]), a1 = up2(xz[i][1]);
            float2 b0 = up2(xr[i][0]), b1 = up2(xr[i][1]);
            float2 c0 = up2(xh[i][0]), c1 = up2(xh[i][1]);
            float2 d0 = up2(hz[i][0]), d1 = up2(hz[i][1]);
            float2 e0 = up2(hr[i][0]), e1 = up2(hr[i][1]);
            float2 f0 = up2(hh[i][0]), f1 = up2(hh[i][1]);
            float zin[4] = {a0.x + d0.x, a0.y + d0.y, a1.x + d1.x, a1.y + d1.y};
            float rin[4] = {b0.x + e0.x, b0.y + e0.y, b1.x + e1.x, b1.y + e1.y};
            float xhv[4] = {c0.x, c0.y, c1.x, c1.y};
            float hhv[4] = {f0.x, f0.y, f1.x, f1.y};
            float4 outv;
            float* ov = (float*)&outv;
#pragma unroll
            for (int j = 0; j < 4; ++j) {
                int u = u0 + j;
                float z  = sigm(zin[j] + b[u]);
                float r  = sigm(rin[j] + b[64 + u]);
                float hc = ftanh(xhv[j] + b[128 + u] + r * hhv[j]);
                float hs = sLS[(r0 + i) * 65 + u];
                ov[j] = z * hs + (1.0f - z) * hc;
            }
            *(float4*)&g_link_state[(size_t)gl * D + u0] = outv;
        }
    }
}

// ---------------- kernel: readout stage 1 ------------------------------------
// g_R1 = selu(PS @ W1 + b1); g_psdot = PS . Wf[256:320]
__global__ void __launch_bounds__(256, 2)
k_r1(const float* __restrict__ W1, const float* __restrict__ b1,
     const float* __restrict__ Wf, int n_paths)
{
    extern __shared__ float sm[];
    float* sPS = sm;              // 64*65 = 4160
    float* sW  = sPS + 4160;      // 64*260 = 16640
    float* sw2 = sW + 16640;      // 64 (Wf[256:320])
    int tid = threadIdx.x;
    int p0 = blockIdx.x * 64;

    for (int idx = tid; idx < 64 * D; idx += 256) {
        int p = idx >> 6, u = idx & 63;
        sPS[p * 65 + u] = (p0 + p < n_paths) ? g_path_state[(size_t)(p0 + p) * D + u] : 0.0f;
    }
    for (int idx = tid; idx < 64 * 64; idx += 256) {
        int k = idx >> 6, q = idx & 63;
        *(float4*)&sW[k * 260 + q * 4] = *(const float4*)&W1[k * 256 + q * 4];
    }
    if (tid < 64) sw2[tid] = Wf[256 + tid];
    __syncthreads();

    int pg = tid >> 4, cg = tid & 15;
    int r0 = pg * 4, c0 = cg * 16;

    ull acc[4][8];
#pragma unroll
    for (int i = 0; i < 4; ++i)
#pragma unroll
        for (int j = 0; j < 8; ++j) acc[i][j] = dup2(0.0f);
    gemm_rows4_x2<16>(sPS, 65, r0, sW, 260, c0, acc);

#pragma unroll
    for (int i = 0; i < 4; ++i) {
        float* dst = &g_R1[(size_t)(p0 + r0 + i) * 256 + c0];
#pragma unroll
        for (int q = 0; q < 4; ++q) {
            float2 va = up2(acc[i][2 * q]);
            float2 vb = up2(acc[i][2 * q + 1]);
            float4 o;
            o.x = selu(va.x + __ldg(&b1[c0 + 4 * q + 0]));
            o.y = selu(va.y + __ldg(&b1[c0 + 4 * q + 1]));
            o.z = selu(vb.x + __ldg(&b1[c0 + 4 * q + 2]));
            o.w = selu(vb.y + __ldg(&b1[c0 + 4 * q + 3]));
            *(float4*)(dst + 4 * q) = o;
        }
    }

    if (tid < 64) {
        float d = 0.0f;
#pragma unroll 8
        for (int u = 0; u < 64; ++u) d += sPS[tid * 65 + u] * sw2[u];
        g_psdot[p0 + tid] = d;
    }
}

// ---------------- kernel: readout stage 2 ------------------------------------
// out = selu(R1 @ W2 + b2) . Wf[0:256] + psdot + bf
__global__ void __launch_bounds__(256, 2)
k_r2(const float* __restrict__ W2, const float* __restrict__ b2,
     const float* __restrict__ Wf, const float* __restrict__ bf,
     float* __restrict__ out, int n_paths)
{
    extern __shared__ float sm[];
    float* sA = sm;              // 64*68 = 4352 (R1 K-chunk)
    float* sW = sA + 4352;       // 64*260 = 16640 (W2 K-chunk)
    int tid = threadIdx.x;
    int p0 = blockIdx.x * 64;
    int pg = tid >> 4, cg = tid & 15;
    int r0 = pg * 4, c0 = cg * 16;

    ull acc[4][8];
#pragma unroll
    for (int i = 0; i < 4; ++i)
#pragma unroll
        for (int j = 0; j < 8; ++j) acc[i][j] = dup2(0.0f);

    for (int kc = 0; kc < 4; ++kc) {
        for (int idx = tid; idx < 64 * 16; idx += 256) {
            int r = idx >> 4, q = idx & 15;
            *(float4*)&sA[r * 68 + q * 4] =
                *(const float4*)&g_R1[(size_t)(p0 + r) * 256 + kc * 64 + q * 4];
        }
        for (int idx = tid; idx < 64 * 64; idx += 256) {
            int k = idx >> 6, q = idx & 63;
            *(float4*)&sW[k * 260 + q * 4] =
                *(const float4*)&W2[(size_t)(kc * 64 + k) * 256 + q * 4];
        }
        __syncthreads();
        gemm_rows4_x2<16>(sA, 68, r0, sW, 260, c0, acc);
        __syncthreads();
    }

    float part[4];
#pragma unroll
    for (int i = 0; i < 4; ++i) {
        float s = 0.0f;
#pragma unroll
        for (int j2 = 0; j2 < 8; ++j2) {
            float2 v = up2(acc[i][j2]);
            int c = c0 + 2 * j2;
            s += selu(v.x + __ldg(&b2[c + 0])) * __ldg(&Wf[c + 0]);
            s += selu(v.y + __ldg(&b2[c + 1])) * __ldg(&Wf[c + 1]);
        }
        part[i] = s;
    }
#pragma unroll
    for (int i = 0; i < 4; ++i) {
#pragma unroll
        for (int off = 8; off > 0; off >>= 1)
            part[i] += __shfl_xor_sync(0xffffffffu, part[i], off, 16);
    }
    if (cg == 0) {
#pragma unroll
        for (int i = 0; i < 4; ++i) {
            int p = p0 + r0 + i;
            if (p < n_paths)
                out[p] = part[i] + g_psdot[p] + __ldg(&bf[0]);
        }
    }
}

// ---------------- host launcher ----------------------------------------------
extern "C" void kernel_launch(void* const* d_in, const int* in_sizes, int n_in,
                              void* d_out, int out_size)
{
    const float* cap  = (const float*)d_in[0];
    const float* traf = (const float*)d_in[1];
    const int*   links= (const int*)d_in[2];
    // d_in[3] = paths, d_in[4] = seqs : structurally e = p*ML + t, unused
    const float* Wx_p = (const float*)d_in[5];
    const float* Wh_p = (const float*)d_in[6];
    const float* b_p  = (const float*)d_in[7];
    const float* Wx_e = (const float*)d_in[8];
    const float* Wh_e = (const float*)d_in[9];
    const float* b_e  = (const float*)d_in[10];
    const float* W1   = (const float*)d_in[11];
    const float* b1   = (const float*)d_in[12];
    const float* W2   = (const float*)d_in[13];
    const float* b2   = (const float*)d_in[14];
    const float* Wf   = (const float*)d_in[15];
    const float* bf   = (const float*)d_in[16];

    int n_links = in_sizes[0];
    int n_paths = in_sizes[1];
    float* out = (float*)d_out;

    const int SM_GX   = (12288 + 64 * 65 + 192) * 4;
    const int SM_SCAN = (12288 + 2 * 64 * SH) * 4;
    const int SM_LGRU = (12288 + 12288 + 4160 + 4160) * 4;
    const int SM_R1   = (4160 + 16640 + 64) * 4;
    const int SM_R2   = (4352 + 16640) * 4;

    static bool attrs_set = false;
    if (!attrs_set) {
        cudaFuncSetAttribute(k_gx,   cudaFuncAttributeMaxDynamicSharedMemorySize, SM_GX);
        cudaFuncSetAttribute(k_scan, cudaFuncAttributeMaxDynamicSharedMemorySize, SM_SCAN);
        cudaFuncSetAttribute(k_lgru, cudaFuncAttributeMaxDynamicSharedMemorySize, SM_LGRU);
        cudaFuncSetAttribute(k_r1,   cudaFuncAttributeMaxDynamicSharedMemorySize, SM_R1);
        cudaFuncSetAttribute(k_r2,   cudaFuncAttributeMaxDynamicSharedMemorySize, SM_R2);
        attrs_set = true;
    }

    k_init<<<((n_links + n_paths) * D + 255) / 256, 256>>>(cap, traf, n_links, n_paths);

    for (int it = 0; it < 3; ++it) {
        bool last = (it == 2);
        k_gx<<<(n_links + 63) / 64, 256, SM_GX>>>(Wx_p, b_p, n_links, last ? 0 : 1);
        k_scan<<<(n_paths + 63) / 64, 256, SM_SCAN>>>(links, Wh_p, n_paths, last ? 0 : 1);
        if (!last)
            k_lgru<<<(n_links + 63) / 64, 512, SM_LGRU>>>(Wx_e, Wh_e, b_e, n_links);
    }

    int gread = (n_paths + 63) / 64;
    k_r1<<<gread, 256, SM_R1>>>(W1, b1, Wf, n_paths);
    k_r2<<<gread, 256, SM_R2>>>(W2, b2, Wf, bf, out, n_paths);
}